// round 1
// baseline (speedup 1.0000x reference)
#include <cuda_runtime.h>
#include <math.h>

// Problem constants (fixed by the dataset)
#define Bn 2048
#define Dn 1024
#define Hn 2048
#define En 16
#define Wn 4
#define Rn 8
#define MAXK 4
#define CANDMAX 16
#define SCALE_C 1.0f

// ---------------- scratch (device globals; no allocation allowed) -----------
__device__ float g_hpre[Bn * Hn];     // 16 MB
__device__ float g_outpre[Bn * Dn];   // 8 MB
__device__ float g_cand_val[Bn * CANDMAX];
__device__ int   g_cand_idx[Bn * CANDMAX];
__device__ int   g_assigned_idx[Bn * MAXK];
__device__ float g_assigned_w[Bn * MAXK];

// ---------------- output layout (flattened concat of the returned tuple) ----
struct Outs {
    float* z;      // [B, D]
    float* probs;  // [B, E]
    float* mask;   // [B, E]   (bool as 0/1 float)
    float* aidx;   // [B, k]   (int as float)
    float* aw;     // [B, k]
    float* chr;    // [1]
    float* ev_e;   // [k*B]
    float* ev_a;   // [k*B]
};

__host__ __device__ __forceinline__ Outs make_outs(float* o, int k) {
    Outs s;
    s.z     = o; o += Bn * Dn;
    s.probs = o; o += Bn * En;
    s.mask  = o; o += Bn * En;
    s.aidx  = o; o += Bn * k;
    s.aw    = o; o += Bn * k;
    s.chr   = o; o += 1;
    s.ev_e  = o; o += (size_t)k * Bn;
    s.ev_a  = o;
    return s;
}

__device__ __forceinline__ float warp_reduce(float v) {
    #pragma unroll
    for (int off = 16; off; off >>= 1) v += __shfl_xor_sync(0xffffffffu, v, off);
    return v;
}

__device__ __forceinline__ float silu_f(float x) {
    return x / (1.0f + expf(-x));
}

// =====================================================================
// Kernel 1: logits -> softmax -> probs, top-cand_k candidate selection,
//           default-init of routed output regions. One warp per token.
// =====================================================================
__global__ void logits_topk_kernel(const float* __restrict__ z,
                                   const float* __restrict__ proto,
                                   const float* __restrict__ ebias,
                                   const int* __restrict__ topk_p,
                                   const int* __restrict__ ban_p,
                                   const float* __restrict__ tau_p,
                                   const float* __restrict__ eps_p,
                                   float* __restrict__ d_out) {
    int gwarp = (blockIdx.x * blockDim.x + threadIdx.x) >> 5;
    int lane  = threadIdx.x & 31;
    if (gwarp >= Bn) return;
    const int b = gwarp;
    const float* zr = z + (size_t)b * Dn;

    float acc[En];
    #pragma unroll
    for (int e = 0; e < En; e++) acc[e] = 0.0f;

    for (int d = lane; d < Dn; d += 32) {
        float zv = zr[d];
        #pragma unroll
        for (int e = 0; e < En; e++) acc[e] += zv * proto[e * Dn + d];
    }
    #pragma unroll
    for (int e = 0; e < En; e++) acc[e] = warp_reduce(acc[e]);

    if (lane != 0) return;

    int k = *topk_p; if (k > En) k = En; if (k > MAXK) k = MAXK; if (k < 1) k = 1;
    int cand_k = 4 * k; if (cand_k < k) cand_k = k; if (cand_k > En) cand_k = En;
    int ban = *ban_p;
    float inv_tau = 1.0f / fmaxf(*tau_p, 1e-6f);
    float eps = *eps_p;

    float lg[En];
    float mx = -1e30f;
    #pragma unroll
    for (int e = 0; e < En; e++) {
        float v = acc[e] * inv_tau + ebias[e];
        if (e == ban) v = -1e9f;
        lg[e] = v;
        mx = fmaxf(mx, v);
    }
    float sum = 0.0f;
    #pragma unroll
    for (int e = 0; e < En; e++) { lg[e] = expf(lg[e] - mx); sum += lg[e]; }
    float inv = 1.0f / sum;

    Outs O = make_outs(d_out, k);
    float pr[En];
    #pragma unroll
    for (int e = 0; e < En; e++) {
        pr[e] = (1.0f - eps) * (lg[e] * inv) + eps / (float)En;
        O.probs[b * En + e] = pr[e];
        O.mask[b * En + e]  = 0.0f;
    }

    // top-cand_k selection, ties -> lowest index first (strict >)
    bool used[En];
    #pragma unroll
    for (int e = 0; e < En; e++) used[e] = false;
    for (int j = 0; j < cand_k; j++) {
        float bv = -1e30f; int bi = 0;
        for (int e = 0; e < En; e++) {
            if (!used[e] && pr[e] > bv) { bv = pr[e]; bi = e; }
        }
        used[bi] = true;
        g_cand_val[b * CANDMAX + j] = bv;
        g_cand_idx[b * CANDMAX + j] = bi;
    }

    for (int s = 0; s < k; s++) {
        g_assigned_idx[b * MAXK + s] = -1;
        g_assigned_w[b * MAXK + s]   = 0.0f;
        O.aidx[b * k + s] = -1.0f;
        O.aw[b * k + s]   = 0.0f;
        O.ev_e[s * Bn + b] = -1.0f;
        O.ev_a[s * Bn + b] = -1.0f;
    }
}

// =====================================================================
// Kernel 2: sequential greedy capacity router. Single warp.
// Within a token, candidates hit distinct experts, so the serial scan is
// equivalent to: take the first k capacity-eligible candidates (ballot +
// prefix popcount). Only the token loop is serial.
// =====================================================================
__global__ void route_kernel(const int* __restrict__ topk_p,
                             const int* __restrict__ cap_p,
                             float* __restrict__ d_out) {
    int lane = threadIdx.x;
    int k = *topk_p; if (k > En) k = En; if (k > MAXK) k = MAXK; if (k < 1) k = 1;
    int cand_k = 4 * k; if (cand_k < k) cand_k = k; if (cand_k > En) cand_k = En;
    int cap_lim = *cap_p; if (cap_lim < 1) cap_lim = 1;

    Outs O = make_outs(d_out, k);

    int cap = 0;   // lane l (< En) holds cap[l]
    int hits = 0;

    float cv = 0.0f; int ci = 0;
    if (lane < cand_k) {
        cv = g_cand_val[lane];
        ci = g_cand_idx[lane];
    }

    for (int t = 0; t < Bn; t++) {
        float cvc = cv; int cic = ci;
        if (lane < cand_k && (t + 1) < Bn) {   // prefetch next token
            cv = g_cand_val[(t + 1) * CANDMAX + lane];
            ci = g_cand_idx[(t + 1) * CANDMAX + lane];
        }
        int capv = __shfl_sync(0xffffffffu, cap, cic & (En - 1));
        bool elig = (lane < cand_k) && (capv < cap_lim);
        unsigned m = __ballot_sync(0xffffffffu, elig);
        int rank = __popc(m & ((1u << lane) - 1u));
        bool take = elig && (rank < k);
        unsigned tm = __ballot_sync(0xffffffffu, take);

        unsigned mm = tm;                       // uniform across warp
        while (mm) {
            int src = __ffs(mm) - 1;
            mm &= mm - 1;
            int ew = __shfl_sync(0xffffffffu, cic, src);
            if (lane == ew) cap++;
        }

        if (take) {
            g_assigned_idx[t * MAXK + rank] = cic;
            g_assigned_w[t * MAXK + rank]   = cvc;
            O.aidx[t * k + rank] = (float)cic;
            O.aw[t * k + rank]   = cvc;
            O.ev_e[rank * Bn + t] = (float)cic;
            O.mask[t * En + cic]  = 1.0f;
            if (lane > 0) hits++;
        }
    }

    #pragma unroll
    for (int off = 16; off; off >>= 1) hits += __shfl_xor_sync(0xffffffffu, hits, off);
    if (lane == 0) O.chr[0] = (float)hits / (float)(Bn * k);
}

// =====================================================================
// Kernel 3/4: SGEMM  C[m,n] = act( sum_k A[m,k]*Wt[n,k] + bias[n] )
// A row-major [M,K], Wt row-major [N,K] (NT gemm). 128x128x16 tiles.
// =====================================================================
#define GBM 128
#define GBN 128
#define GBK 16
#define GTM 8
#define GTN 8

template <int ACT>
__global__ void __launch_bounds__(256)
gemm_nt_kernel(const float* __restrict__ A, const float* __restrict__ Wt,
               const float* __restrict__ bias, float* __restrict__ C,
               int M, int N, int K) {
    __shared__ float As[GBK][GBM];
    __shared__ float Bs[GBK][GBN];

    const int bx = blockIdx.x;  // N tile
    const int by = blockIdx.y;  // M tile
    const int tid = threadIdx.x;
    const int tx = tid & 15;    // N
    const int ty = tid >> 4;    // M

    float acc[GTM][GTN];
    #pragma unroll
    for (int i = 0; i < GTM; i++)
        #pragma unroll
        for (int j = 0; j < GTN; j++) acc[i][j] = 0.0f;

    const int lrow = tid >> 2;          // 0..63
    const int lcol = (tid & 3) * 4;     // 0,4,8,12
    const float* Aptr = A  + (size_t)(by * GBM) * K;
    const float* Bptr = Wt + (size_t)(bx * GBN) * K;

    for (int k0 = 0; k0 < K; k0 += GBK) {
        #pragma unroll
        for (int i = 0; i < GBM; i += 64) {
            float4 v = *(const float4*)(Aptr + (size_t)(lrow + i) * K + k0 + lcol);
            As[lcol + 0][lrow + i] = v.x;
            As[lcol + 1][lrow + i] = v.y;
            As[lcol + 2][lrow + i] = v.z;
            As[lcol + 3][lrow + i] = v.w;
        }
        #pragma unroll
        for (int i = 0; i < GBN; i += 64) {
            float4 v = *(const float4*)(Bptr + (size_t)(lrow + i) * K + k0 + lcol);
            Bs[lcol + 0][lrow + i] = v.x;
            Bs[lcol + 1][lrow + i] = v.y;
            Bs[lcol + 2][lrow + i] = v.z;
            Bs[lcol + 3][lrow + i] = v.w;
        }
        __syncthreads();

        #pragma unroll
        for (int kk = 0; kk < GBK; kk++) {
            float ra[GTM], rb[GTN];
            #pragma unroll
            for (int i = 0; i < GTM; i += 4) {
                float4 v = *(const float4*)(&As[kk][ty * GTM + i]);
                ra[i] = v.x; ra[i + 1] = v.y; ra[i + 2] = v.z; ra[i + 3] = v.w;
            }
            #pragma unroll
            for (int j = 0; j < GTN; j += 4) {
                float4 v = *(const float4*)(&Bs[kk][tx * GTN + j]);
                rb[j] = v.x; rb[j + 1] = v.y; rb[j + 2] = v.z; rb[j + 3] = v.w;
            }
            #pragma unroll
            for (int i = 0; i < GTM; i++)
                #pragma unroll
                for (int j = 0; j < GTN; j++) acc[i][j] += ra[i] * rb[j];
        }
        __syncthreads();
    }

    #pragma unroll
    for (int i = 0; i < GTM; i++) {
        int m = by * GBM + ty * GTM + i;
        #pragma unroll
        for (int j = 0; j < GTN; j++) {
            int n = bx * GBN + tx * GTN + j;
            float v = acc[i][j] + bias[n];
            if (ACT) v = silu_f(v);
            C[(size_t)m * N + n] = v;
        }
    }
}

// =====================================================================
// Kernel 5: adapter selection + LoRA apply + final output.
// One block (256 thr = 8 warps) per token.
// =====================================================================
__global__ void __launch_bounds__(256)
adapter_kernel(const float* __restrict__ z,
               const float* __restrict__ ak,
               const float* __restrict__ a1, const float* __restrict__ b1,
               const float* __restrict__ a2, const float* __restrict__ b2,
               const int* __restrict__ topk_p,
               float* __restrict__ d_out) {
    __shared__ float s_z[Dn];
    __shared__ float s_hp[Hn];
    __shared__ float s_h[Hn];
    __shared__ float s_t1[Rn];
    __shared__ float s_t2[Rn];
    __shared__ float s_sc[Wn];
    __shared__ int   s_widx;

    const int b = blockIdx.x;
    const int tid = threadIdx.x;
    const int lane = tid & 31;
    const int warp = tid >> 5;   // 8 warps

    int k = *topk_p; if (k > En) k = En; if (k > MAXK) k = MAXK; if (k < 1) k = 1;
    Outs O = make_outs(d_out, k);

    for (int i = tid; i < Dn; i += 256) s_z[i] = z[(size_t)b * Dn + i];
    for (int i = tid; i < Hn; i += 256) s_hp[i] = g_hpre[(size_t)b * Hn + i];

    float accd[Dn / 256];
    #pragma unroll
    for (int i = 0; i < Dn / 256; i++) accd[i] = 0.0f;
    __syncthreads();

    for (int s = 0; s < k; s++) {
        int e = g_assigned_idx[b * MAXK + s];
        if (e >= 0) {
            float wgt = g_assigned_w[b * MAXK + s];

            // --- adapter selection: argmax_w  z . adapter_keys[e, w] ---
            if (warp < Wn) {
                const float* akr = ak + (size_t)(e * Wn + warp) * Dn;
                float p = 0.0f;
                for (int d = lane; d < Dn; d += 32) p += s_z[d] * akr[d];
                p = warp_reduce(p);
                if (lane == 0) s_sc[warp] = p;
            }
            __syncthreads();
            if (tid == 0) {
                float bv = s_sc[0]; int bi = 0;
                #pragma unroll
                for (int w2 = 1; w2 < Wn; w2++)
                    if (s_sc[w2] > bv) { bv = s_sc[w2]; bi = w2; }
                s_widx = bi;
                O.ev_a[s * Bn + b] = (float)bi;
            }
            __syncthreads();
            const int base = e * Wn + s_widx;

            // --- t1[r] = z . A1[e,w,r,:] ---
            {
                const float* A1r = a1 + ((size_t)base * Rn + warp) * Dn;
                float p = 0.0f;
                for (int d = lane; d < Dn; d += 32) p += s_z[d] * A1r[d];
                p = warp_reduce(p);
                if (lane == 0) s_t1[warp] = p;
            }
            __syncthreads();

            // --- h[h] = silu(h_pre + SCALE * t1 . B1[h,:]) ---
            for (int h = tid; h < Hn; h += 256) {
                const float* B1r = b1 + ((size_t)base * Hn + h) * Rn;
                float d1 = 0.0f;
                #pragma unroll
                for (int r = 0; r < Rn; r++) d1 += s_t1[r] * B1r[r];
                s_h[h] = silu_f(s_hp[h] + d1 * SCALE_C);
            }
            __syncthreads();

            // --- t2[r] = h . A2[e,w,r,:] ---
            {
                const float* A2r = a2 + ((size_t)base * Rn + warp) * Hn;
                float p = 0.0f;
                for (int h2 = lane; h2 < Hn; h2 += 32) p += s_h[h2] * A2r[h2];
                p = warp_reduce(p);
                if (lane == 0) s_t2[warp] = p;
            }
            __syncthreads();

            // --- y = out_pre + SCALE * t2 . B2[d,:];  acc += w * y ---
            #pragma unroll
            for (int i = 0; i < Dn / 256; i++) {
                int d = tid + i * 256;
                const float* B2r = b2 + ((size_t)base * Dn + d) * Rn;
                float d2 = 0.0f;
                #pragma unroll
                for (int r = 0; r < Rn; r++) d2 += s_t2[r] * B2r[r];
                accd[i] += wgt * (g_outpre[(size_t)b * Dn + d] + d2 * SCALE_C);
            }
            __syncthreads();
        }
    }

    #pragma unroll
    for (int i = 0; i < Dn / 256; i++) {
        int d = tid + i * 256;
        O.z[(size_t)b * Dn + d] = s_z[d] + accd[i];
    }
}

// =====================================================================
// launch
// =====================================================================
extern "C" void kernel_launch(void* const* d_in, const int* in_sizes, int n_in,
                              void* d_out, int out_size) {
    const float* z     = (const float*)d_in[0];
    const int*   topk  = (const int*)  d_in[1];
    const int*   cap   = (const int*)  d_in[2];
    const int*   ban   = (const int*)  d_in[3];
    const float* tau   = (const float*)d_in[4];
    const float* eps   = (const float*)d_in[5];
    const float* fc1w  = (const float*)d_in[6];
    const float* fc1b  = (const float*)d_in[7];
    const float* fc2w  = (const float*)d_in[8];
    const float* fc2b  = (const float*)d_in[9];
    const float* proto = (const float*)d_in[10];
    const float* ak    = (const float*)d_in[11];
    const float* ebias = (const float*)d_in[12];
    const float* a1    = (const float*)d_in[13];
    const float* b1    = (const float*)d_in[14];
    const float* a2    = (const float*)d_in[15];
    const float* b2    = (const float*)d_in[16];
    float* out = (float*)d_out;

    float *hpre_ptr = nullptr, *outpre_ptr = nullptr;
    cudaGetSymbolAddress((void**)&hpre_ptr, g_hpre);
    cudaGetSymbolAddress((void**)&outpre_ptr, g_outpre);

    // 1) logits / probs / candidates / output defaults
    logits_topk_kernel<<<Bn / 4, 128>>>(z, proto, ebias, topk, ban, tau, eps, out);

    // 2) sequential greedy capacity routing (single warp)
    route_kernel<<<1, 32>>>(topk, cap, out);

    // 3) h_pre = silu(z @ fc1_w^T + fc1_b)   [B,H]
    gemm_nt_kernel<1><<<dim3(Hn / GBN, Bn / GBM), 256>>>(z, fc1w, fc1b, hpre_ptr,
                                                         Bn, Hn, Dn);

    // 4) out_pre = h_pre @ fc2_w^T + fc2_b   [B,D]
    gemm_nt_kernel<0><<<dim3(Dn / GBN, Bn / GBM), 256>>>(hpre_ptr, fc2w, fc2b, outpre_ptr,
                                                         Bn, Dn, Hn);

    // 5) adapter select + LoRA deltas + final combine
    adapter_kernel<<<Bn, 256>>>(z, ak, a1, b1, a2, b2, topk, out);
}

// round 2
// speedup vs baseline: 1.3402x; 1.3402x over previous
#include <cuda_runtime.h>
#include <math.h>

// Problem constants (fixed by the dataset)
#define Bn 2048
#define Dn 1024
#define Hn 2048
#define En 16
#define Wn 4
#define Rn 8
#define MAXK 4
#define CANDMAX 16
#define SCALE_C 1.0f

// ---------------- scratch (device globals; no allocation allowed) -----------
__device__ float g_hpre[Bn * Hn];     // 16 MB
__device__ float g_outpre[Bn * Dn];   // 8 MB
__device__ float g_cand_val[Bn * CANDMAX];
__device__ int   g_cand_idx[Bn * CANDMAX];
__device__ int   g_assigned_idx[Bn * MAXK];
__device__ float g_assigned_w[Bn * MAXK];

// ---------------- output layout (flattened concat of the returned tuple) ----
struct Outs {
    float* z;      // [B, D]
    float* probs;  // [B, E]
    float* mask;   // [B, E]   (bool as 0/1 float)
    float* aidx;   // [B, k]   (int as float)
    float* aw;     // [B, k]
    float* chr;    // [1]
    float* ev_e;   // [k*B]
    float* ev_a;   // [k*B]
};

__host__ __device__ __forceinline__ Outs make_outs(float* o, int k) {
    Outs s;
    s.z     = o; o += Bn * Dn;
    s.probs = o; o += Bn * En;
    s.mask  = o; o += Bn * En;
    s.aidx  = o; o += Bn * k;
    s.aw    = o; o += Bn * k;
    s.chr   = o; o += 1;
    s.ev_e  = o; o += (size_t)k * Bn;
    s.ev_a  = o;
    return s;
}

__device__ __forceinline__ float warp_reduce(float v) {
    #pragma unroll
    for (int off = 16; off; off >>= 1) v += __shfl_xor_sync(0xffffffffu, v, off);
    return v;
}

__device__ __forceinline__ float silu_f(float x) {
    return x / (1.0f + expf(-x));
}

__device__ __forceinline__ unsigned f2tf32(float f) {
    unsigned u;
    asm volatile("cvt.rna.tf32.f32 %0, %1;" : "=r"(u) : "f"(f));
    return u;
}

__device__ __forceinline__ void mma_tf32(float* d, const unsigned* a, const unsigned* b) {
    asm volatile(
        "mma.sync.aligned.m16n8k8.row.col.f32.tf32.tf32.f32 "
        "{%0,%1,%2,%3}, {%4,%5,%6,%7}, {%8,%9}, {%0,%1,%2,%3};"
        : "+f"(d[0]), "+f"(d[1]), "+f"(d[2]), "+f"(d[3])
        : "r"(a[0]), "r"(a[1]), "r"(a[2]), "r"(a[3]), "r"(b[0]), "r"(b[1]));
}

// =====================================================================
// Kernel 1: logits -> softmax -> probs, top-cand_k candidate selection,
//           default-init of routed output regions. One warp per token.
// =====================================================================
__global__ void logits_topk_kernel(const float* __restrict__ z,
                                   const float* __restrict__ proto,
                                   const float* __restrict__ ebias,
                                   const int* __restrict__ topk_p,
                                   const int* __restrict__ ban_p,
                                   const float* __restrict__ tau_p,
                                   const float* __restrict__ eps_p,
                                   float* __restrict__ d_out) {
    int gwarp = (blockIdx.x * blockDim.x + threadIdx.x) >> 5;
    int lane  = threadIdx.x & 31;
    if (gwarp >= Bn) return;
    const int b = gwarp;
    const float* zr = z + (size_t)b * Dn;

    float acc[En];
    #pragma unroll
    for (int e = 0; e < En; e++) acc[e] = 0.0f;

    for (int d = lane; d < Dn; d += 32) {
        float zv = zr[d];
        #pragma unroll
        for (int e = 0; e < En; e++) acc[e] += zv * proto[e * Dn + d];
    }
    #pragma unroll
    for (int e = 0; e < En; e++) acc[e] = warp_reduce(acc[e]);

    if (lane != 0) return;

    int k = *topk_p; if (k > En) k = En; if (k > MAXK) k = MAXK; if (k < 1) k = 1;
    int cand_k = 4 * k; if (cand_k < k) cand_k = k; if (cand_k > En) cand_k = En;
    int ban = *ban_p;
    float inv_tau = 1.0f / fmaxf(*tau_p, 1e-6f);
    float eps = *eps_p;

    float lg[En];
    float mx = -1e30f;
    #pragma unroll
    for (int e = 0; e < En; e++) {
        float v = acc[e] * inv_tau + ebias[e];
        if (e == ban) v = -1e9f;
        lg[e] = v;
        mx = fmaxf(mx, v);
    }
    float sum = 0.0f;
    #pragma unroll
    for (int e = 0; e < En; e++) { lg[e] = expf(lg[e] - mx); sum += lg[e]; }
    float inv = 1.0f / sum;

    Outs O = make_outs(d_out, k);
    float pr[En];
    #pragma unroll
    for (int e = 0; e < En; e++) {
        pr[e] = (1.0f - eps) * (lg[e] * inv) + eps / (float)En;
        O.probs[b * En + e] = pr[e];
        O.mask[b * En + e]  = 0.0f;
    }

    // top-cand_k selection, ties -> lowest index first (strict >)
    bool used[En];
    #pragma unroll
    for (int e = 0; e < En; e++) used[e] = false;
    for (int j = 0; j < cand_k; j++) {
        float bv = -1e30f; int bi = 0;
        for (int e = 0; e < En; e++) {
            if (!used[e] && pr[e] > bv) { bv = pr[e]; bi = e; }
        }
        used[bi] = true;
        g_cand_val[b * CANDMAX + j] = bv;
        g_cand_idx[b * CANDMAX + j] = bi;
    }

    for (int s = 0; s < k; s++) {
        g_assigned_idx[b * MAXK + s] = -1;
        g_assigned_w[b * MAXK + s]   = 0.0f;
        O.aidx[b * k + s] = -1.0f;
        O.aw[b * k + s]   = 0.0f;
        O.ev_e[s * Bn + b] = -1.0f;
        O.ev_a[s * Bn + b] = -1.0f;
    }
}

// =====================================================================
// Kernel 2: sequential greedy capacity router. Single warp.
// =====================================================================
__global__ void route_kernel(const int* __restrict__ topk_p,
                             const int* __restrict__ cap_p,
                             float* __restrict__ d_out) {
    int lane = threadIdx.x;
    int k = *topk_p; if (k > En) k = En; if (k > MAXK) k = MAXK; if (k < 1) k = 1;
    int cand_k = 4 * k; if (cand_k < k) cand_k = k; if (cand_k > En) cand_k = En;
    int cap_lim = *cap_p; if (cap_lim < 1) cap_lim = 1;

    Outs O = make_outs(d_out, k);

    int cap = 0;   // lane l (< En) holds cap[l]
    int hits = 0;

    float cv = 0.0f; int ci = 0;
    if (lane < cand_k) {
        cv = g_cand_val[lane];
        ci = g_cand_idx[lane];
    }

    for (int t = 0; t < Bn; t++) {
        float cvc = cv; int cic = ci;
        if (lane < cand_k && (t + 1) < Bn) {   // prefetch next token
            cv = g_cand_val[(t + 1) * CANDMAX + lane];
            ci = g_cand_idx[(t + 1) * CANDMAX + lane];
        }
        int capv = __shfl_sync(0xffffffffu, cap, cic & (En - 1));
        bool elig = (lane < cand_k) && (capv < cap_lim);
        unsigned m = __ballot_sync(0xffffffffu, elig);
        int rank = __popc(m & ((1u << lane) - 1u));
        bool take = elig && (rank < k);
        unsigned tm = __ballot_sync(0xffffffffu, take);

        unsigned mm = tm;                       // uniform across warp
        while (mm) {
            int src = __ffs(mm) - 1;
            mm &= mm - 1;
            int ew = __shfl_sync(0xffffffffu, cic, src);
            if (lane == ew) cap++;
        }

        if (take) {
            g_assigned_idx[t * MAXK + rank] = cic;
            g_assigned_w[t * MAXK + rank]   = cvc;
            O.aidx[t * k + rank] = (float)cic;
            O.aw[t * k + rank]   = cvc;
            O.ev_e[rank * Bn + t] = (float)cic;
            O.mask[t * En + cic]  = 1.0f;
            if (lane > 0) hits++;
        }
    }

    #pragma unroll
    for (int off = 16; off; off >>= 1) hits += __shfl_xor_sync(0xffffffffu, hits, off);
    if (lane == 0) O.chr[0] = (float)hits / (float)(Bn * k);
}

// =====================================================================
// Kernel 3/4: TF32 tensor-core GEMM.
// C[m,n] = act( sum_k A[m,k]*Wt[n,k] + bias[n] )   (NT gemm)
// Block tile 128x128x32, 8 warps, warp tile 32x64, mma.m16n8k8.tf32.
// SMEM rows padded to 36 floats: fragment loads hit banks (4g+tg) -> all
// 32 banks distinct (conflict-free); STS.128 conflict-free per octet.
// =====================================================================
#define TBM 128
#define TBN 128
#define TBK 32
#define LDP 36   // padded row stride (floats)

template <int ACT>
__global__ void __launch_bounds__(256)
gemm_tf32_kernel(const float* __restrict__ A, const float* __restrict__ Wt,
                 const float* __restrict__ bias, float* __restrict__ C,
                 int M, int N, int K) {
    __shared__ unsigned As[TBM * LDP];
    __shared__ unsigned Bs[TBN * LDP];

    const int bx = blockIdx.x;  // N tile
    const int by = blockIdx.y;  // M tile
    const int tid = threadIdx.x;
    const int warp = tid >> 5;
    const int lane = tid & 31;
    const int g  = lane >> 2;   // 0..7
    const int tg = lane & 3;    // 0..3

    const int wm = (warp & 3) * 32;   // warp m base within tile (4 warps in m)
    const int wn = (warp >> 2) * 64;  // warp n base within tile (2 warps in n)

    // staging loads: thread t loads 4 float4 (rows r0 + 32*i, 16B chunk fq)
    const int r0 = tid >> 3;        // 0..31
    const int fq = tid & 7;         // 0..7  (float4 index within 32-float row)

    const float* Aptr = A  + (size_t)(by * TBM) * K;
    const float* Bptr = Wt + (size_t)(bx * TBN) * K;

    float acc[2][8][4];
    #pragma unroll
    for (int i = 0; i < 2; i++)
        #pragma unroll
        for (int j = 0; j < 8; j++)
            #pragma unroll
            for (int c = 0; c < 4; c++) acc[i][j][c] = 0.0f;

    float4 ra[4], rb[4];
    // prologue load (k0 = 0)
    #pragma unroll
    for (int i = 0; i < 4; i++) {
        ra[i] = *(const float4*)(Aptr + (size_t)(r0 + 32 * i) * K + fq * 4);
        rb[i] = *(const float4*)(Bptr + (size_t)(r0 + 32 * i) * K + fq * 4);
    }

    const int KIT = K / TBK;
    for (int kt = 0; kt < KIT; kt++) {
        // store staged tile (cvt to tf32 with round-to-nearest)
        #pragma unroll
        for (int i = 0; i < 4; i++) {
            uint4 ua, ub;
            ua.x = f2tf32(ra[i].x); ua.y = f2tf32(ra[i].y);
            ua.z = f2tf32(ra[i].z); ua.w = f2tf32(ra[i].w);
            ub.x = f2tf32(rb[i].x); ub.y = f2tf32(rb[i].y);
            ub.z = f2tf32(rb[i].z); ub.w = f2tf32(rb[i].w);
            *(uint4*)(&As[(r0 + 32 * i) * LDP + fq * 4]) = ua;
            *(uint4*)(&Bs[(r0 + 32 * i) * LDP + fq * 4]) = ub;
        }
        __syncthreads();

        // prefetch next tile
        if (kt + 1 < KIT) {
            int k0 = (kt + 1) * TBK;
            #pragma unroll
            for (int i = 0; i < 4; i++) {
                ra[i] = *(const float4*)(Aptr + (size_t)(r0 + 32 * i) * K + k0 + fq * 4);
                rb[i] = *(const float4*)(Bptr + (size_t)(r0 + 32 * i) * K + k0 + fq * 4);
            }
        }

        // compute: 4 k-steps of 8
        #pragma unroll
        for (int kk = 0; kk < 4; kk++) {
            unsigned afr[2][4];
            #pragma unroll
            for (int mi = 0; mi < 2; mi++) {
                int row = wm + mi * 16 + g;
                afr[mi][0] = As[row * LDP + kk * 8 + tg];
                afr[mi][1] = As[(row + 8) * LDP + kk * 8 + tg];
                afr[mi][2] = As[row * LDP + kk * 8 + tg + 4];
                afr[mi][3] = As[(row + 8) * LDP + kk * 8 + tg + 4];
            }
            unsigned bfr[8][2];
            #pragma unroll
            for (int ni = 0; ni < 8; ni++) {
                int col = wn + ni * 8 + g;
                bfr[ni][0] = Bs[col * LDP + kk * 8 + tg];
                bfr[ni][1] = Bs[col * LDP + kk * 8 + tg + 4];
            }
            #pragma unroll
            for (int mi = 0; mi < 2; mi++)
                #pragma unroll
                for (int ni = 0; ni < 8; ni++)
                    mma_tf32(acc[mi][ni], afr[mi], bfr[ni]);
        }
        __syncthreads();
    }

    // epilogue
    #pragma unroll
    for (int mi = 0; mi < 2; mi++) {
        int row0 = by * TBM + wm + mi * 16 + g;
        #pragma unroll
        for (int ni = 0; ni < 8; ni++) {
            int col = bx * TBN + wn + ni * 8 + 2 * tg;
            float b0 = bias[col], b1 = bias[col + 1];
            float v0 = acc[mi][ni][0] + b0;
            float v1 = acc[mi][ni][1] + b1;
            float v2 = acc[mi][ni][2] + b0;
            float v3 = acc[mi][ni][3] + b1;
            if (ACT) { v0 = silu_f(v0); v1 = silu_f(v1); v2 = silu_f(v2); v3 = silu_f(v3); }
            *(float2*)(&C[(size_t)row0 * N + col])       = make_float2(v0, v1);
            *(float2*)(&C[(size_t)(row0 + 8) * N + col]) = make_float2(v2, v3);
        }
    }
}

// =====================================================================
// Kernel 5: adapter selection + LoRA apply + final output.
// One block (256 thr = 8 warps) per token.
// =====================================================================
__global__ void __launch_bounds__(256)
adapter_kernel(const float* __restrict__ z,
               const float* __restrict__ ak,
               const float* __restrict__ a1, const float* __restrict__ b1,
               const float* __restrict__ a2, const float* __restrict__ b2,
               const int* __restrict__ topk_p,
               float* __restrict__ d_out) {
    __shared__ float s_z[Dn];
    __shared__ float s_hp[Hn];
    __shared__ float s_h[Hn];
    __shared__ float s_t1[Rn];
    __shared__ float s_t2[Rn];
    __shared__ float s_sc[Wn];
    __shared__ int   s_widx;

    const int b = blockIdx.x;
    const int tid = threadIdx.x;
    const int lane = tid & 31;
    const int warp = tid >> 5;   // 8 warps

    int k = *topk_p; if (k > En) k = En; if (k > MAXK) k = MAXK; if (k < 1) k = 1;
    Outs O = make_outs(d_out, k);

    for (int i = tid; i < Dn; i += 256) s_z[i] = z[(size_t)b * Dn + i];
    for (int i = tid; i < Hn; i += 256) s_hp[i] = g_hpre[(size_t)b * Hn + i];

    float accd[Dn / 256];
    #pragma unroll
    for (int i = 0; i < Dn / 256; i++) accd[i] = 0.0f;
    __syncthreads();

    for (int s = 0; s < k; s++) {
        int e = g_assigned_idx[b * MAXK + s];
        if (e >= 0) {
            float wgt = g_assigned_w[b * MAXK + s];

            // --- adapter selection: argmax_w  z . adapter_keys[e, w] ---
            if (warp < Wn) {
                const float* akr = ak + (size_t)(e * Wn + warp) * Dn;
                float p = 0.0f;
                for (int d = lane; d < Dn; d += 32) p += s_z[d] * akr[d];
                p = warp_reduce(p);
                if (lane == 0) s_sc[warp] = p;
            }
            __syncthreads();
            if (tid == 0) {
                float bv = s_sc[0]; int bi = 0;
                #pragma unroll
                for (int w2 = 1; w2 < Wn; w2++)
                    if (s_sc[w2] > bv) { bv = s_sc[w2]; bi = w2; }
                s_widx = bi;
                O.ev_a[s * Bn + b] = (float)bi;
            }
            __syncthreads();
            const int base = e * Wn + s_widx;

            // --- t1[r] = z . A1[e,w,r,:] ---
            {
                const float* A1r = a1 + ((size_t)base * Rn + warp) * Dn;
                float p = 0.0f;
                for (int d = lane; d < Dn; d += 32) p += s_z[d] * A1r[d];
                p = warp_reduce(p);
                if (lane == 0) s_t1[warp] = p;
            }
            __syncthreads();

            // --- h[h] = silu(h_pre + SCALE * t1 . B1[h,:]) ---
            for (int h = tid; h < Hn; h += 256) {
                const float* B1r = b1 + ((size_t)base * Hn + h) * Rn;
                float d1 = 0.0f;
                #pragma unroll
                for (int r = 0; r < Rn; r++) d1 += s_t1[r] * B1r[r];
                s_h[h] = silu_f(s_hp[h] + d1 * SCALE_C);
            }
            __syncthreads();

            // --- t2[r] = h . A2[e,w,r,:] ---
            {
                const float* A2r = a2 + ((size_t)base * Rn + warp) * Hn;
                float p = 0.0f;
                for (int h2 = lane; h2 < Hn; h2 += 32) p += s_h[h2] * A2r[h2];
                p = warp_reduce(p);
                if (lane == 0) s_t2[warp] = p;
            }
            __syncthreads();

            // --- y = out_pre + SCALE * t2 . B2[d,:];  acc += w * y ---
            #pragma unroll
            for (int i = 0; i < Dn / 256; i++) {
                int d = tid + i * 256;
                const float* B2r = b2 + ((size_t)base * Dn + d) * Rn;
                float d2 = 0.0f;
                #pragma unroll
                for (int r = 0; r < Rn; r++) d2 += s_t2[r] * B2r[r];
                accd[i] += wgt * (g_outpre[(size_t)b * Dn + d] + d2 * SCALE_C);
            }
            __syncthreads();
        }
    }

    #pragma unroll
    for (int i = 0; i < Dn / 256; i++) {
        int d = tid + i * 256;
        O.z[(size_t)b * Dn + d] = s_z[d] + accd[i];
    }
}

// =====================================================================
// launch
// =====================================================================
extern "C" void kernel_launch(void* const* d_in, const int* in_sizes, int n_in,
                              void* d_out, int out_size) {
    const float* z     = (const float*)d_in[0];
    const int*   topk  = (const int*)  d_in[1];
    const int*   cap   = (const int*)  d_in[2];
    const int*   ban   = (const int*)  d_in[3];
    const float* tau   = (const float*)d_in[4];
    const float* eps   = (const float*)d_in[5];
    const float* fc1w  = (const float*)d_in[6];
    const float* fc1b  = (const float*)d_in[7];
    const float* fc2w  = (const float*)d_in[8];
    const float* fc2b  = (const float*)d_in[9];
    const float* proto = (const float*)d_in[10];
    const float* ak    = (const float*)d_in[11];
    const float* ebias = (const float*)d_in[12];
    const float* a1    = (const float*)d_in[13];
    const float* b1    = (const float*)d_in[14];
    const float* a2    = (const float*)d_in[15];
    const float* b2    = (const float*)d_in[16];
    float* out = (float*)d_out;

    float *hpre_ptr = nullptr, *outpre_ptr = nullptr;
    cudaGetSymbolAddress((void**)&hpre_ptr, g_hpre);
    cudaGetSymbolAddress((void**)&outpre_ptr, g_outpre);

    // 1) logits / probs / candidates / output defaults
    logits_topk_kernel<<<Bn / 4, 128>>>(z, proto, ebias, topk, ban, tau, eps, out);

    // 2) sequential greedy capacity routing (single warp)
    route_kernel<<<1, 32>>>(topk, cap, out);

    // 3) h_pre = silu(z @ fc1_w^T + fc1_b)   [B,H]
    gemm_tf32_kernel<1><<<dim3(Hn / TBN, Bn / TBM), 256>>>(z, fc1w, fc1b, hpre_ptr,
                                                           Bn, Hn, Dn);

    // 4) out_pre = h_pre @ fc2_w^T + fc2_b   [B,D]
    gemm_tf32_kernel<0><<<dim3(Dn / TBN, Bn / TBM), 256>>>(hpre_ptr, fc2w, fc2b, outpre_ptr,
                                                           Bn, Dn, Hn);

    // 5) adapter select + LoRA deltas + final combine
    adapter_kernel<<<Bn, 256>>>(z, ak, a1, b1, a2, b2, topk, out);
}

// round 3
// speedup vs baseline: 3.2505x; 2.4253x over previous
#include <cuda_runtime.h>
#include <math.h>

// Problem constants (fixed by the dataset)
#define Bn 2048
#define Dn 1024
#define Hn 2048
#define En 16
#define Wn 4
#define Rn 8
#define MAXK 4
#define CANDMAX 16
#define SCALE_C 1.0f

// ---------------- scratch (device globals; no allocation allowed) -----------
__device__ float g_hpre[Bn * Hn];     // 16 MB
__device__ float g_outpre[Bn * Dn];   // 8 MB
__device__ float g_cand_val[Bn * CANDMAX];
__device__ unsigned long long g_pack[Bn];   // candidate expert ids, 4-bit nibbles
__device__ int   g_assigned_idx[Bn * MAXK];
__device__ float g_assigned_w[Bn * MAXK];

// ---------------- output layout (flattened concat of the returned tuple) ----
struct Outs {
    float* z;      // [B, D]
    float* probs;  // [B, E]
    float* mask;   // [B, E]
    float* aidx;   // [B, k]
    float* aw;     // [B, k]
    float* chr;    // [1]
    float* ev_e;   // [k*B]
    float* ev_a;   // [k*B]
};

__host__ __device__ __forceinline__ Outs make_outs(float* o, int k) {
    Outs s;
    s.z     = o; o += Bn * Dn;
    s.probs = o; o += Bn * En;
    s.mask  = o; o += Bn * En;
    s.aidx  = o; o += Bn * k;
    s.aw    = o; o += Bn * k;
    s.chr   = o; o += 1;
    s.ev_e  = o; o += (size_t)k * Bn;
    s.ev_a  = o;
    return s;
}

__device__ __forceinline__ float warp_reduce(float v) {
    #pragma unroll
    for (int off = 16; off; off >>= 1) v += __shfl_xor_sync(0xffffffffu, v, off);
    return v;
}

__device__ __forceinline__ float silu_f(float x) {
    return x / (1.0f + expf(-x));
}

__device__ __forceinline__ unsigned f2tf32(float f) {
    unsigned u;
    asm volatile("cvt.rna.tf32.f32 %0, %1;" : "=r"(u) : "f"(f));
    return u;
}

__device__ __forceinline__ void mma_tf32(float* d, const unsigned* a, const unsigned* b) {
    asm volatile(
        "mma.sync.aligned.m16n8k8.row.col.f32.tf32.tf32.f32 "
        "{%0,%1,%2,%3}, {%4,%5,%6,%7}, {%8,%9}, {%0,%1,%2,%3};"
        : "+f"(d[0]), "+f"(d[1]), "+f"(d[2]), "+f"(d[3])
        : "r"(a[0]), "r"(a[1]), "r"(a[2]), "r"(a[3]), "r"(b[0]), "r"(b[1]));
}

// =====================================================================
// Kernel 1: logits -> softmax -> probs, top-cand_k candidates (packed),
//           default-init of routed output regions. One warp per token.
// =====================================================================
__global__ void logits_topk_kernel(const float* __restrict__ z,
                                   const float* __restrict__ proto,
                                   const float* __restrict__ ebias,
                                   const int* __restrict__ topk_p,
                                   const int* __restrict__ ban_p,
                                   const float* __restrict__ tau_p,
                                   const float* __restrict__ eps_p,
                                   float* __restrict__ d_out) {
    int gwarp = (blockIdx.x * blockDim.x + threadIdx.x) >> 5;
    int lane  = threadIdx.x & 31;
    if (gwarp >= Bn) return;
    const int b = gwarp;
    const float* zr = z + (size_t)b * Dn;

    float acc[En];
    #pragma unroll
    for (int e = 0; e < En; e++) acc[e] = 0.0f;

    for (int d = lane; d < Dn; d += 32) {
        float zv = zr[d];
        #pragma unroll
        for (int e = 0; e < En; e++) acc[e] += zv * proto[e * Dn + d];
    }
    #pragma unroll
    for (int e = 0; e < En; e++) acc[e] = warp_reduce(acc[e]);

    if (lane != 0) return;

    int k = *topk_p; if (k > En) k = En; if (k > MAXK) k = MAXK; if (k < 1) k = 1;
    int cand_k = 4 * k; if (cand_k < k) cand_k = k; if (cand_k > En) cand_k = En;
    int ban = *ban_p;
    float inv_tau = 1.0f / fmaxf(*tau_p, 1e-6f);
    float eps = *eps_p;

    float lg[En];
    float mx = -1e30f;
    #pragma unroll
    for (int e = 0; e < En; e++) {
        float v = acc[e] * inv_tau + ebias[e];
        if (e == ban) v = -1e9f;
        lg[e] = v;
        mx = fmaxf(mx, v);
    }
    float sum = 0.0f;
    #pragma unroll
    for (int e = 0; e < En; e++) { lg[e] = expf(lg[e] - mx); sum += lg[e]; }
    float inv = 1.0f / sum;

    Outs O = make_outs(d_out, k);
    float pr[En];
    #pragma unroll
    for (int e = 0; e < En; e++) {
        pr[e] = (1.0f - eps) * (lg[e] * inv) + eps / (float)En;
        O.probs[b * En + e] = pr[e];
        O.mask[b * En + e]  = 0.0f;
    }

    // top-cand_k selection, ties -> lowest index first (strict >)
    bool used[En];
    #pragma unroll
    for (int e = 0; e < En; e++) used[e] = false;
    unsigned long long pk = 0ull;
    for (int j = 0; j < cand_k; j++) {
        float bv = -1e30f; int bi = 0;
        for (int e = 0; e < En; e++) {
            if (!used[e] && pr[e] > bv) { bv = pr[e]; bi = e; }
        }
        used[bi] = true;
        g_cand_val[b * CANDMAX + j] = bv;
        pk |= ((unsigned long long)bi) << (4 * j);
    }
    g_pack[b] = pk;

    for (int s = 0; s < k; s++) {
        g_assigned_idx[b * MAXK + s] = -1;
        g_assigned_w[b * MAXK + s]   = 0.0f;
        O.aidx[b * k + s] = -1.0f;
        O.aw[b * k + s]   = 0.0f;
        O.ev_e[s * Bn + b] = -1.0f;
        O.ev_a[s * Bn + b] = -1.0f;
    }
}

// =====================================================================
// Kernel 2: batched greedy capacity router. Single warp, 32 tokens/batch.
// Insight: per-token decisions depend ONLY on the closed-expert set
// (monotone; <= En transitions). Decide 32 tokens in parallel against
// the current closed mask, detect the earliest capacity violation via
// per-expert ballots, commit the valid prefix, update closed, repeat.
// =====================================================================
__global__ void route_kernel(const int* __restrict__ topk_p,
                             const int* __restrict__ cap_p,
                             float* __restrict__ d_out) {
    const int lane = threadIdx.x;
    int k = *topk_p; if (k > En) k = En; if (k > MAXK) k = MAXK; if (k < 1) k = 1;
    int cand_k = 4 * k; if (cand_k < k) cand_k = k; if (cand_k > En) cand_k = En;
    int cap_lim = *cap_p; if (cap_lim < 1) cap_lim = 1;

    Outs O = make_outs(d_out, k);

    int cap = 0;            // lane < En holds cap[lane]
    unsigned closed = 0;    // uniform 16-bit closed-expert mask
    int hits = 0;

    int t0 = 0;
    while (t0 < Bn) {
        const int t = t0 + lane;
        const bool has = (t < Bn);
        unsigned long long pk = has ? g_pack[t] : 0ull;

        // local decision vs current closed mask
        unsigned take = 0;        // expert-id bits taken by my token
        unsigned slotcand = 0;    // candidate index per slot (4 bits each)
        int nslots = 0;
        int myhits = 0;
        if (has) {
            for (int j = 0; j < cand_k; j++) {
                int e = (int)((pk >> (4 * j)) & 15ull);
                if (!((closed >> e) & 1u) && nslots < k) {
                    take |= (1u << e);
                    slotcand |= ((unsigned)j) << (4 * nslots);
                    if (j > 0) myhits++;
                    nslots++;
                }
            }
        }

        // per-expert take bitvectors over the 32-token batch
        unsigned mybits = 0;
        #pragma unroll
        for (int e = 0; e < En; e++) {
            unsigned bb = __ballot_sync(0xffffffffu, (take >> e) & 1u);
            if (lane == e) mybits = bb;
        }
        int cnt = __popc(mybits);

        // violation: open expert whose cumulative takes exceed remaining cap
        bool viol = (lane < En) && !((closed >> lane) & 1u) && (cap + cnt > cap_lim);
        unsigned vm = __ballot_sync(0xffffffffu, viol);
        int pstar = 32;
        if (vm) {
            int myp = 32;
            if (viol) {
                int rem = cap_lim - cap;        // >= 1 for open experts
                unsigned m = mybits;
                for (int i = 0; i < rem; i++) m &= m - 1;
                myp = __ffs(m) - 1;             // first exceeding token pos
            }
            #pragma unroll
            for (int off = 16; off; off >>= 1) {
                int o = __shfl_xor_sync(0xffffffffu, myp, off);
                myp = min(myp, o);
            }
            pstar = myp;                         // uniform; >= 1 always
        }

        unsigned commit_prefix = (pstar >= 32) ? 0xffffffffu : ((1u << pstar) - 1u);
        if (lane < En) cap += __popc(mybits & commit_prefix);

        if (has && lane < pstar) {
            for (int s = 0; s < nslots; s++) {
                int j = (int)((slotcand >> (4 * s)) & 15u);
                int e = (int)((pk >> (4 * j)) & 15ull);
                float v = g_cand_val[t * CANDMAX + j];
                g_assigned_idx[t * MAXK + s] = e;
                g_assigned_w[t * MAXK + s]   = v;
                O.aidx[t * k + s] = (float)e;
                O.aw[t * k + s]   = v;
                O.ev_e[s * Bn + t] = (float)e;
                O.mask[t * En + e] = 1.0f;
            }
            hits += myhits;
        }

        closed = __ballot_sync(0xffffffffu, (lane < En) && (cap >= cap_lim)) & 0xffffu;
        t0 += pstar;
    }

    #pragma unroll
    for (int off = 16; off; off >>= 1) hits += __shfl_xor_sync(0xffffffffu, hits, off);
    if (lane == 0) O.chr[0] = (float)hits / (float)(Bn * k);
}

// =====================================================================
// Kernel 3/4: TF32 tensor-core GEMM, double-buffered SMEM pipeline.
// C[m,n] = act( sum_k A[m,k]*Wt[n,k] + bias[n] )   (NT gemm)
// Block tile 128x128x32, 8 warps, warp tile 32x64, mma.m16n8k8.tf32.
// =====================================================================
#define TBM 128
#define TBN 128
#define TBK 32
#define LDP 36   // padded row stride (floats)
#define GPITCH ((TBM + TBN) * LDP)

template <int ACT>
__global__ void __launch_bounds__(256, 1)
gemm_tf32_kernel(const float* __restrict__ A, const float* __restrict__ Wt,
                 const float* __restrict__ bias, float* __restrict__ C,
                 int M, int N, int K) {
    extern __shared__ unsigned smem_u[];

    const int bx = blockIdx.x;  // N tile
    const int by = blockIdx.y;  // M tile
    const int tid = threadIdx.x;
    const int warp = tid >> 5;
    const int lane = tid & 31;
    const int g  = lane >> 2;   // 0..7
    const int tg = lane & 3;    // 0..3

    const int wm = (warp & 3) * 32;
    const int wn = (warp >> 2) * 64;

    const int r0 = tid >> 3;        // 0..31
    const int fq = tid & 7;         // 0..7

    const float* Aptr = A  + (size_t)(by * TBM) * K;
    const float* Bptr = Wt + (size_t)(bx * TBN) * K;

    float acc[2][8][4];
    #pragma unroll
    for (int i = 0; i < 2; i++)
        #pragma unroll
        for (int j = 0; j < 8; j++)
            #pragma unroll
            for (int c = 0; c < 4; c++) acc[i][j][c] = 0.0f;

    float4 ra[4], rb[4];
    // prologue: load + store tile 0
    #pragma unroll
    for (int i = 0; i < 4; i++) {
        ra[i] = *(const float4*)(Aptr + (size_t)(r0 + 32 * i) * K + fq * 4);
        rb[i] = *(const float4*)(Bptr + (size_t)(r0 + 32 * i) * K + fq * 4);
    }
    {
        unsigned* As0 = smem_u;
        unsigned* Bs0 = smem_u + TBM * LDP;
        #pragma unroll
        for (int i = 0; i < 4; i++) {
            uint4 ua, ub;
            ua.x = f2tf32(ra[i].x); ua.y = f2tf32(ra[i].y);
            ua.z = f2tf32(ra[i].z); ua.w = f2tf32(ra[i].w);
            ub.x = f2tf32(rb[i].x); ub.y = f2tf32(rb[i].y);
            ub.z = f2tf32(rb[i].z); ub.w = f2tf32(rb[i].w);
            *(uint4*)(&As0[(r0 + 32 * i) * LDP + fq * 4]) = ua;
            *(uint4*)(&Bs0[(r0 + 32 * i) * LDP + fq * 4]) = ub;
        }
    }
    __syncthreads();

    const int KIT = K / TBK;
    for (int kt = 0; kt < KIT; kt++) {
        const int cur = kt & 1;
        const bool more = (kt + 1 < KIT);
        unsigned* AsC = smem_u + cur * GPITCH;
        unsigned* BsC = AsC + TBM * LDP;

        // prefetch next tile into registers (hidden under MMA compute)
        if (more) {
            int k0 = (kt + 1) * TBK;
            #pragma unroll
            for (int i = 0; i < 4; i++) {
                ra[i] = *(const float4*)(Aptr + (size_t)(r0 + 32 * i) * K + k0 + fq * 4);
                rb[i] = *(const float4*)(Bptr + (size_t)(r0 + 32 * i) * K + k0 + fq * 4);
            }
        }

        // compute on current buffer
        #pragma unroll
        for (int kk = 0; kk < 4; kk++) {
            unsigned afr[2][4];
            #pragma unroll
            for (int mi = 0; mi < 2; mi++) {
                int row = wm + mi * 16 + g;
                afr[mi][0] = AsC[row * LDP + kk * 8 + tg];
                afr[mi][1] = AsC[(row + 8) * LDP + kk * 8 + tg];
                afr[mi][2] = AsC[row * LDP + kk * 8 + tg + 4];
                afr[mi][3] = AsC[(row + 8) * LDP + kk * 8 + tg + 4];
            }
            unsigned bfr[8][2];
            #pragma unroll
            for (int ni = 0; ni < 8; ni++) {
                int col = wn + ni * 8 + g;
                bfr[ni][0] = BsC[col * LDP + kk * 8 + tg];
                bfr[ni][1] = BsC[col * LDP + kk * 8 + tg + 4];
            }
            #pragma unroll
            for (int mi = 0; mi < 2; mi++)
                #pragma unroll
                for (int ni = 0; ni < 8; ni++)
                    mma_tf32(acc[mi][ni], afr[mi], bfr[ni]);
        }

        // store next tile into alternate buffer
        if (more) {
            unsigned* AsN = smem_u + (1 - cur) * GPITCH;
            unsigned* BsN = AsN + TBM * LDP;
            #pragma unroll
            for (int i = 0; i < 4; i++) {
                uint4 ua, ub;
                ua.x = f2tf32(ra[i].x); ua.y = f2tf32(ra[i].y);
                ua.z = f2tf32(ra[i].z); ua.w = f2tf32(ra[i].w);
                ub.x = f2tf32(rb[i].x); ub.y = f2tf32(rb[i].y);
                ub.z = f2tf32(rb[i].z); ub.w = f2tf32(rb[i].w);
                *(uint4*)(&AsN[(r0 + 32 * i) * LDP + fq * 4]) = ua;
                *(uint4*)(&BsN[(r0 + 32 * i) * LDP + fq * 4]) = ub;
            }
        }
        __syncthreads();
    }

    // epilogue
    #pragma unroll
    for (int mi = 0; mi < 2; mi++) {
        int row0 = by * TBM + wm + mi * 16 + g;
        #pragma unroll
        for (int ni = 0; ni < 8; ni++) {
            int col = bx * TBN + wn + ni * 8 + 2 * tg;
            float b0 = bias[col], b1 = bias[col + 1];
            float v0 = acc[mi][ni][0] + b0;
            float v1 = acc[mi][ni][1] + b1;
            float v2 = acc[mi][ni][2] + b0;
            float v3 = acc[mi][ni][3] + b1;
            if (ACT) { v0 = silu_f(v0); v1 = silu_f(v1); v2 = silu_f(v2); v3 = silu_f(v3); }
            *(float2*)(&C[(size_t)row0 * N + col])       = make_float2(v0, v1);
            *(float2*)(&C[(size_t)(row0 + 8) * N + col]) = make_float2(v2, v3);
        }
    }
}

// =====================================================================
// Kernel 5: adapter selection + LoRA apply + final output.
// One block (256 thr = 8 warps) per token; two slots processed
// concurrently by two 4-warp groups.
// =====================================================================
__global__ void __launch_bounds__(256)
adapter_kernel(const float* __restrict__ z,
               const float* __restrict__ ak,
               const float* __restrict__ a1, const float* __restrict__ b1,
               const float* __restrict__ a2, const float* __restrict__ b2,
               const int* __restrict__ topk_p,
               float* __restrict__ d_out) {
    __shared__ float s_z[Dn];
    __shared__ float s_hp[Hn];
    __shared__ float s_h[2][Hn];
    __shared__ float s_t1[2][Rn];
    __shared__ float s_t2[2][Rn];
    __shared__ float s_sc[2][Wn];
    __shared__ int   s_base[2];
    __shared__ float s_wgt[2];
    __shared__ int   s_valid[2];

    const int b = blockIdx.x;
    const int tid = threadIdx.x;
    const int lane = tid & 31;
    const int warp = tid >> 5;     // 0..7
    const int group = warp >> 2;   // 0,1
    const int wig = warp & 3;      // warp in group
    const int gt = tid & 127;      // thread in group

    int k = *topk_p; if (k > En) k = En; if (k > MAXK) k = MAXK; if (k < 1) k = 1;
    Outs O = make_outs(d_out, k);

    for (int i = tid; i < Dn; i += 256) s_z[i] = z[(size_t)b * Dn + i];
    for (int i = tid; i < Hn; i += 256) s_hp[i] = g_hpre[(size_t)b * Hn + i];

    float opre[Dn / 256];
    float accd[Dn / 256];
    #pragma unroll
    for (int i = 0; i < Dn / 256; i++) {
        opre[i] = g_outpre[(size_t)b * Dn + tid + i * 256];
        accd[i] = 0.0f;
    }
    __syncthreads();

    for (int s0 = 0; s0 < k; s0 += 2) {
        const int sA = s0 + group;
        const bool act = (sA < k);
        int e = -1;
        float wgt = 0.0f;
        if (act) {
            e   = g_assigned_idx[b * MAXK + sA];
            wgt = g_assigned_w[b * MAXK + sA];
        }
        const bool valid = act && (e >= 0);

        // phase 1: adapter-key dots (warp wig handles key wig)
        if (valid) {
            const float* akr = ak + (size_t)(e * Wn + wig) * Dn;
            float p0 = 0.0f, p1 = 0.0f;
            for (int d = lane; d < Dn; d += 64) {
                p0 += s_z[d] * akr[d];
                p1 += s_z[d + 32] * akr[d + 32];
            }
            float p = warp_reduce(p0 + p1);
            if (lane == 0) s_sc[group][wig] = p;
        }
        __syncthreads();

        // phase 2: argmax + publish base/wgt/valid
        if (gt == 0) {
            if (valid) {
                float bv = s_sc[group][0]; int bi = 0;
                #pragma unroll
                for (int w2 = 1; w2 < Wn; w2++)
                    if (s_sc[group][w2] > bv) { bv = s_sc[group][w2]; bi = w2; }
                s_base[group] = e * Wn + bi;
                s_wgt[group] = wgt;
                s_valid[group] = 1;
                O.ev_a[sA * Bn + b] = (float)bi;
            } else {
                s_valid[group] = 0;
            }
        }
        __syncthreads();

        const int base = s_base[group];

        // phase 3: t1[r] = z . A1[base, r, :]  (warp handles 2 r's)
        if (valid) {
            const float* A1r0 = a1 + ((size_t)base * Rn + 2 * wig) * Dn;
            const float* A1r1 = A1r0 + Dn;
            float q0 = 0.0f, q1 = 0.0f;
            for (int d = lane; d < Dn; d += 32) {
                float zv = s_z[d];
                q0 += zv * A1r0[d];
                q1 += zv * A1r1[d];
            }
            q0 = warp_reduce(q0);
            q1 = warp_reduce(q1);
            if (lane == 0) { s_t1[group][2 * wig] = q0; s_t1[group][2 * wig + 1] = q1; }
        }
        __syncthreads();

        // phase 4: h = silu(h_pre + t1 . B1)
        if (valid) {
            float t1r[Rn];
            #pragma unroll
            for (int r = 0; r < Rn; r++) t1r[r] = s_t1[group][r];
            for (int h = gt; h < Hn; h += 128) {
                const float* B1r = b1 + ((size_t)base * Hn + h) * Rn;
                float d1 = 0.0f;
                #pragma unroll
                for (int r = 0; r < Rn; r++) d1 += t1r[r] * B1r[r];
                s_h[group][h] = silu_f(s_hp[h] + d1 * SCALE_C);
            }
        }
        __syncthreads();

        // phase 5: t2[r] = h . A2[base, r, :]
        if (valid) {
            const float* A2r0 = a2 + ((size_t)base * Rn + 2 * wig) * Hn;
            const float* A2r1 = A2r0 + Hn;
            float q0 = 0.0f, q1 = 0.0f;
            for (int h2 = lane; h2 < Hn; h2 += 32) {
                float hv = s_h[group][h2];
                q0 += hv * A2r0[h2];
                q1 += hv * A2r1[h2];
            }
            q0 = warp_reduce(q0);
            q1 = warp_reduce(q1);
            if (lane == 0) { s_t2[group][2 * wig] = q0; s_t2[group][2 * wig + 1] = q1; }
        }
        __syncthreads();

        // phase 6: accumulate both groups' deltas into per-thread acc
        #pragma unroll
        for (int gg = 0; gg < 2; gg++) {
            if (s_valid[gg]) {
                const int bs = s_base[gg];
                const float wg = s_wgt[gg];
                float t2r[Rn];
                #pragma unroll
                for (int r = 0; r < Rn; r++) t2r[r] = s_t2[gg][r];
                #pragma unroll
                for (int i = 0; i < Dn / 256; i++) {
                    int d = tid + i * 256;
                    const float* B2r = b2 + ((size_t)bs * Dn + d) * Rn;
                    float d2 = 0.0f;
                    #pragma unroll
                    for (int r = 0; r < Rn; r++) d2 += t2r[r] * B2r[r];
                    accd[i] += wg * (opre[i] + d2 * SCALE_C);
                }
            }
        }
        __syncthreads();
    }

    #pragma unroll
    for (int i = 0; i < Dn / 256; i++) {
        int d = tid + i * 256;
        O.z[(size_t)b * Dn + d] = s_z[d] + accd[i];
    }
}

// =====================================================================
// launch
// =====================================================================
extern "C" void kernel_launch(void* const* d_in, const int* in_sizes, int n_in,
                              void* d_out, int out_size) {
    const float* z     = (const float*)d_in[0];
    const int*   topk  = (const int*)  d_in[1];
    const int*   cap   = (const int*)  d_in[2];
    const int*   ban   = (const int*)  d_in[3];
    const float* tau   = (const float*)d_in[4];
    const float* eps   = (const float*)d_in[5];
    const float* fc1w  = (const float*)d_in[6];
    const float* fc1b  = (const float*)d_in[7];
    const float* fc2w  = (const float*)d_in[8];
    const float* fc2b  = (const float*)d_in[9];
    const float* proto = (const float*)d_in[10];
    const float* ak    = (const float*)d_in[11];
    const float* ebias = (const float*)d_in[12];
    const float* a1    = (const float*)d_in[13];
    const float* b1    = (const float*)d_in[14];
    const float* a2    = (const float*)d_in[15];
    const float* b2    = (const float*)d_in[16];
    float* out = (float*)d_out;

    float *hpre_ptr = nullptr, *outpre_ptr = nullptr;
    cudaGetSymbolAddress((void**)&hpre_ptr, g_hpre);
    cudaGetSymbolAddress((void**)&outpre_ptr, g_outpre);

    const int gemm_smem = 2 * (TBM + TBN) * LDP * sizeof(unsigned);  // 73728
    cudaFuncSetAttribute(gemm_tf32_kernel<1>,
                         cudaFuncAttributeMaxDynamicSharedMemorySize, gemm_smem);
    cudaFuncSetAttribute(gemm_tf32_kernel<0>,
                         cudaFuncAttributeMaxDynamicSharedMemorySize, gemm_smem);

    // 1) logits / probs / candidates / output defaults
    logits_topk_kernel<<<Bn / 4, 128>>>(z, proto, ebias, topk, ban, tau, eps, out);

    // 2) batched greedy capacity routing (single warp)
    route_kernel<<<1, 32>>>(topk, cap, out);

    // 3) h_pre = silu(z @ fc1_w^T + fc1_b)   [B,H]
    gemm_tf32_kernel<1><<<dim3(Hn / TBN, Bn / TBM), 256, gemm_smem>>>(
        z, fc1w, fc1b, hpre_ptr, Bn, Hn, Dn);

    // 4) out_pre = h_pre @ fc2_w^T + fc2_b   [B,D]
    gemm_tf32_kernel<0><<<dim3(Dn / TBN, Bn / TBM), 256, gemm_smem>>>(
        hpre_ptr, fc2w, fc2b, outpre_ptr, Bn, Dn, Hn);

    // 5) adapter select + LoRA deltas + final combine
    adapter_kernel<<<Bn, 256>>>(z, ak, a1, b1, a2, b2, topk, out);
}